// round 4
// baseline (speedup 1.0000x reference)
#include <cuda_runtime.h>
#include <cuda_fp16.h>
#include <math.h>
#include <stdint.h>

// ---------------- problem constants ----------------
constexpr int E    = 8;
constexpr int D    = 512;
constexpr int HH   = 1024;
constexpr int NTOK = 8192;
constexpr int AMAX = NTOK * 2;     // exactly 2 assignments per token
constexpr int NTILE = 32;          // routing tiles of 256 tokens

// ---------------- device scratch (static; no allocation) ----------------
__device__ __half g_xh[(size_t)NTOK * D];
__device__ __half g_xl[(size_t)NTOK * D];
__device__ __half g_w1h[(size_t)E * HH * D];   // [E][H][D]  (w1 transposed)
__device__ __half g_w1l[(size_t)E * HH * D];
__device__ __half g_w2h[(size_t)E * D * HH];   // [E][D][H]  (w2 transposed)
__device__ __half g_w2l[(size_t)E * D * HH];
__device__ __half g_hh[(size_t)AMAX * HH];     // gelu(h) hi
__device__ __half g_hl[(size_t)AMAX * HH];     // gelu(h) lo
__device__ float  g_y[(size_t)AMAX * D];

__device__ int   g_tok[AMAX];
__device__ float g_wt[AMAX];
__device__ int   g_slot[NTOK * 2];
__device__ int   g_topi[NTOK * 2];
__device__ float g_topw[NTOK * 2];
__device__ int   g_count[E];
__device__ int   g_offs[E + 1];
__device__ int   g_tilecnt[NTILE][E];
__device__ int   g_tileoff[NTILE][E];

// ---------------- PTX helpers (all baseline sm_80/sm_90, no 'a' features) ----
__device__ __forceinline__ uint32_t smem_u32(const void* p) {
    uint32_t a;
    asm("{ .reg .u64 t; cvta.to.shared.u64 t, %1; cvt.u32.u64 %0, t; }" : "=r"(a) : "l"(p));
    return a;
}
__device__ __forceinline__ void cp_async16(uint32_t dst, const void* src) {
    asm volatile("cp.async.cg.shared.global [%0], [%1], 16;" :: "r"(dst), "l"(src));
}
#define CP_COMMIT() asm volatile("cp.async.commit_group;" ::: "memory")
#define CP_WAIT(n)  asm volatile("cp.async.wait_group %0;" :: "n"(n) : "memory")

__device__ __forceinline__ void ldmatrix_x4(uint32_t* f, uint32_t addr) {
    asm volatile("ldmatrix.sync.aligned.m8n8.x4.shared.b16 {%0,%1,%2,%3}, [%4];"
                 : "=r"(f[0]), "=r"(f[1]), "=r"(f[2]), "=r"(f[3]) : "r"(addr));
}
__device__ __forceinline__ uint32_t lds_u32(uint32_t addr) {
    uint32_t v;
    asm volatile("ld.shared.b32 %0, [%1];" : "=r"(v) : "r"(addr));
    return v;
}
__device__ __forceinline__ void mma_16816(float* c, const uint32_t* a, const uint32_t* b) {
    asm volatile("mma.sync.aligned.m16n8k16.row.col.f32.f16.f16.f32 "
                 "{%0,%1,%2,%3}, {%4,%5,%6,%7}, {%8,%9}, {%0,%1,%2,%3};"
                 : "+f"(c[0]), "+f"(c[1]), "+f"(c[2]), "+f"(c[3])
                 : "r"(a[0]), "r"(a[1]), "r"(a[2]), "r"(a[3]), "r"(b[0]), "r"(b[1]));
}

__device__ __forceinline__ float gelu_exact(float v) {
    return 0.5f * v * (1.0f + erff(v * 0.70710678118654752f));
}
__device__ __forceinline__ void split_h(float v, __half& h, __half& l) {
    h = __float2half_rn(v);
    l = __float2half_rn(v - __half2float(h));
}

// ---------------- 1) router ----------------
__global__ void router_kernel(const float* __restrict__ x,
                              const float* __restrict__ gw,
                              const float* __restrict__ gb,
                              float* __restrict__ probs) {
    int t = blockIdx.x * blockDim.y + threadIdx.y;
    if (t >= NTOK) return;
    int lane = threadIdx.x;
    float acc[E];
#pragma unroll
    for (int e = 0; e < E; e++) acc[e] = 0.0f;
    const float* xr = x + (size_t)t * D;
    for (int d = lane; d < D; d += 32) {
        float xv = xr[d];
        const float* g = gw + d * E;
#pragma unroll
        for (int e = 0; e < E; e++) acc[e] += xv * g[e];
    }
#pragma unroll
    for (int e = 0; e < E; e++)
#pragma unroll
        for (int off = 16; off > 0; off >>= 1)
            acc[e] += __shfl_xor_sync(0xffffffffu, acc[e], off);
    if (lane == 0) {
        float p[E]; float mx = -1e30f;
#pragma unroll
        for (int e = 0; e < E; e++) { p[e] = acc[e] + gb[e]; mx = fmaxf(mx, p[e]); }
        float s = 0.0f;
#pragma unroll
        for (int e = 0; e < E; e++) { p[e] = expf(p[e] - mx); s += p[e]; }
        float inv = 1.0f / s;
#pragma unroll
        for (int e = 0; e < E; e++) { p[e] *= inv; probs[(size_t)t * E + e] = p[e]; }
        int i0 = 0; float v0 = p[0];
#pragma unroll
        for (int e = 1; e < E; e++) if (p[e] > v0) { v0 = p[e]; i0 = e; }
        int i1 = -1; float v1 = -1.0f;
#pragma unroll
        for (int e = 0; e < E; e++) if (e != i0 && p[e] > v1) { v1 = p[e]; i1 = e; }
        float ws = 1.0f / (v0 + v1);
        g_topi[2 * t] = i0; g_topi[2 * t + 1] = i1;
        g_topw[2 * t] = v0 * ws; g_topw[2 * t + 1] = v1 * ws;
    }
}

// ---------------- 2) per-tile counts ----------------
__global__ void tilecnt_kernel() {
    __shared__ int cnt[E];
    int t = blockIdx.x * 256 + threadIdx.x;
    if (threadIdx.x < E) cnt[threadIdx.x] = 0;
    __syncthreads();
    int e0 = g_topi[2 * t], e1 = g_topi[2 * t + 1];
    int lane = threadIdx.x & 31;
#pragma unroll
    for (int e = 0; e < E; e++) {
        unsigned m = __ballot_sync(0xffffffffu, e0 == e || e1 == e);
        if (lane == 0) atomicAdd(&cnt[e], __popc(m));
    }
    __syncthreads();
    if (threadIdx.x < E) g_tilecnt[blockIdx.x][threadIdx.x] = cnt[threadIdx.x];
}

// ---------------- 3) offsets ----------------
__global__ void offsets_kernel() {
    if (threadIdx.x != 0) return;
    int tot[E];
    for (int e = 0; e < E; e++) { int s = 0; for (int b = 0; b < NTILE; b++) s += g_tilecnt[b][e]; tot[e] = s; }
    int s = 0;
    for (int e = 0; e < E; e++) { g_offs[e] = s; g_count[e] = tot[e]; s += tot[e]; }
    g_offs[E] = s;
    for (int e = 0; e < E; e++) { int r = g_offs[e]; for (int b = 0; b < NTILE; b++) { g_tileoff[b][e] = r; r += g_tilecnt[b][e]; } }
}

// ---------------- 4) deterministic scatter ----------------
__global__ void scatter_kernel() {
    __shared__ int wcnt[8][E];
    int t = blockIdx.x * 256 + threadIdx.x;
    int lane = threadIdx.x & 31, w = threadIdx.x >> 5;
    int e0 = g_topi[2 * t], e1 = g_topi[2 * t + 1];
    unsigned mask[E];
#pragma unroll
    for (int e = 0; e < E; e++) {
        mask[e] = __ballot_sync(0xffffffffu, e0 == e || e1 == e);
        if (lane == 0) wcnt[w][e] = __popc(mask[e]);
    }
    __syncthreads();
#pragma unroll
    for (int e = 0; e < E; e++) {
        if (e == e0 || e == e1) {
            int pre = 0;
            for (int ww = 0; ww < w; ww++) pre += wcnt[ww][e];
            int pos = g_tileoff[blockIdx.x][e] + pre + __popc(mask[e] & ((1u << lane) - 1));
            int which = (e == e0) ? 0 : 1;
            g_tok[pos] = t;
            g_wt[pos] = g_topw[2 * t + which];
            g_slot[2 * t + which] = pos;
        }
    }
}

// ---------------- 5) conversions (fp32 -> fp16 hi/lo) ----------------
__global__ void conv_x_kernel(const float* __restrict__ x) {
    int i = blockIdx.x * blockDim.x + threadIdx.x;     // float4 index
    if (i >= NTOK * D / 4) return;
    float4 v = ((const float4*)x)[i];
    __half h0, h1, h2, h3, l0, l1, l2, l3;
    split_h(v.x, h0, l0); split_h(v.y, h1, l1);
    split_h(v.z, h2, l2); split_h(v.w, h3, l3);
    __half2* ph = (__half2*)g_xh;
    __half2* pl = (__half2*)g_xl;
    ph[2 * i]     = __halves2half2(h0, h1);
    ph[2 * i + 1] = __halves2half2(h2, h3);
    pl[2 * i]     = __halves2half2(l0, l1);
    pl[2 * i + 1] = __halves2half2(l2, l3);
}

// transpose w1[e][d][h] -> g_w1{h,l}[e][h][d]
__global__ void conv_w1_kernel(const float* __restrict__ w1) {
    __shared__ float t[32][33];
    int h0 = blockIdx.x * 32, d0 = blockIdx.y * 32, e = blockIdx.z;
#pragma unroll
    for (int i = 0; i < 4; i++) {
        int r = threadIdx.y + 8 * i;
        t[r][threadIdx.x] = w1[((size_t)e * D + d0 + r) * HH + h0 + threadIdx.x];
    }
    __syncthreads();
#pragma unroll
    for (int i = 0; i < 4; i++) {
        int r = threadIdx.y + 8 * i;
        float v = t[threadIdx.x][r];
        size_t o = ((size_t)e * HH + h0 + r) * D + d0 + threadIdx.x;
        __half h, l; split_h(v, h, l);
        g_w1h[o] = h; g_w1l[o] = l;
    }
}
// transpose w2[e][h][d] -> g_w2{h,l}[e][d][h]
__global__ void conv_w2_kernel(const float* __restrict__ w2) {
    __shared__ float t[32][33];
    int d0 = blockIdx.x * 32, h0 = blockIdx.y * 32, e = blockIdx.z;
#pragma unroll
    for (int i = 0; i < 4; i++) {
        int r = threadIdx.y + 8 * i;
        t[r][threadIdx.x] = w2[((size_t)e * HH + h0 + r) * D + d0 + threadIdx.x];
    }
    __syncthreads();
#pragma unroll
    for (int i = 0; i < 4; i++) {
        int r = threadIdx.y + 8 * i;
        float v = t[threadIdx.x][r];
        size_t o = ((size_t)e * D + d0 + r) * HH + h0 + threadIdx.x;
        __half h, l; split_h(v, h, l);
        g_w2h[o] = h; g_w2l[o] = l;
    }
}

// ---------------- 6) HMMA grouped GEMM ----------------
// CTA tile 128x128, BK=32 halves, 3-stage cp.async pipeline.
// smem matrix: 128 rows x 40 halves (stride 80B). Ah|Al|Bh|Bl per stage.
constexpr int MAT_B   = 128 * 80;          // 10240 B
constexpr int STAGE_B = 4 * MAT_B;         // 40960 B
constexpr int SMEM_GEMM = 1024 + 3 * STAGE_B; // 123904 B

template <int KTOT, int NFULL, bool GATHER, bool GELUQ>
__global__ __launch_bounds__(256, 1) void moe_gemm(const float* __restrict__ bias) {
    constexpr int NC = KTOT / 32;
    const int e = blockIdx.z;
    const int cnt = g_count[e];
    const int m0 = blockIdx.y * 128;
    if (m0 >= cnt) return;
    const int base = g_offs[e];
    const int n0 = blockIdx.x * 128;

    extern __shared__ char smem[];
    const uint32_t sb = smem_u32(smem);
    int* s_tok = (int*)smem;               // 128 ints
    const uint32_t TILE = sb + 1024;

    const int tid = threadIdx.x;
    const int lane = tid & 31;
    const int wid = tid >> 5;
    const int wm = (wid >> 2) * 64;        // warp m offset (0,64)
    const int wn = (wid & 3) * 32;         // warp n offset (0..96)

    const __half* Ah = GATHER ? g_xh : g_hh;
    const __half* Al = GATHER ? g_xl : g_hl;
    const __half* Bh = GELUQ ? g_w1h : g_w2h;
    const __half* Bl = GELUQ ? g_w1l : g_w2l;

    if (tid < 128) {
        int r = base + m0 + tid; if (r > AMAX - 1) r = AMAX - 1;
        s_tok[tid] = GATHER ? g_tok[r] : r;
    }
    __syncthreads();

    // per-thread loader slots: 2048 16B-chunks / 256 threads = 8
    const __half* srcp[8];
    uint32_t dstoff[8];
#pragma unroll
    for (int i = 0; i < 8; i++) {
        int g = i * 256 + tid;
        int mat = g >> 9, idx = g & 511, row = idx >> 2, seg = idx & 3;
        const __half* sp;
        if (mat < 2) {
            sp = (mat == 0 ? Ah : Al) + (size_t)s_tok[row] * KTOT + seg * 8;
        } else {
            sp = (mat == 2 ? Bh : Bl) + ((size_t)e * NFULL + n0 + row) * KTOT + seg * 8;
        }
        srcp[i] = sp;
        dstoff[i] = (uint32_t)(mat * MAT_B + row * 80 + seg * 16);
    }

    auto load_stage = [&](int c) {
        uint32_t stg = TILE + (c % 3) * STAGE_B;
        int k0 = c * 32;
#pragma unroll
        for (int i = 0; i < 8; i++) cp_async16(stg + dstoff[i], srcp[i] + k0);
    };

    float acc[2][4][4];   // [m-pair? no: 4 m-tiles]
#pragma unroll
    for (int a = 0; a < 2; a++)
#pragma unroll
        for (int t = 0; t < 4; t++)
#pragma unroll
            for (int j = 0; j < 4; j++) acc[a][t][j] = 0.0f;
    // flatten: acc4[t][n][4] -> use acc as [4][4][4]? keep separate array:
    float C[4][4][4];
#pragma unroll
    for (int t = 0; t < 4; t++)
#pragma unroll
        for (int n = 0; n < 4; n++)
#pragma unroll
            for (int j = 0; j < 4; j++) C[t][n][j] = 0.0f;

    load_stage(0); CP_COMMIT();
    load_stage(1); CP_COMMIT();

    for (int c = 0; c < NC; c++) {
        __syncthreads();
        if (c + 2 < NC) load_stage(c + 2);
        CP_COMMIT();
        CP_WAIT(2);
        __syncthreads();

        const uint32_t stg = TILE + (c % 3) * STAGE_B;
#pragma unroll
        for (int s = 0; s < 32; s += 16) {
            uint32_t ah[4][4], al[4][4];
#pragma unroll
            for (int t = 0; t < 4; t++) {
                uint32_t ra = stg + (wm + t * 16 + (lane & 15)) * 80
                                  + (s + ((lane >> 4) << 3)) * 2;
                ldmatrix_x4(ah[t], ra);
                ldmatrix_x4(al[t], ra + MAT_B);
            }
            uint32_t bh[4][2], bl[4][2];
#pragma unroll
            for (int n = 0; n < 4; n++) {
                uint32_t rb = stg + 2 * MAT_B + (wn + n * 8 + (lane >> 2)) * 80
                                  + (s + ((lane & 3) << 1)) * 2;
                bh[n][0] = lds_u32(rb);
                bh[n][1] = lds_u32(rb + 16);
                bl[n][0] = lds_u32(rb + MAT_B);
                bl[n][1] = lds_u32(rb + MAT_B + 16);
            }
#pragma unroll
            for (int t = 0; t < 4; t++)
#pragma unroll
                for (int n = 0; n < 4; n++) {
                    mma_16816(C[t][n], ah[t], bh[n]);
                    mma_16816(C[t][n], ah[t], bl[n]);
                    mma_16816(C[t][n], al[t], bh[n]);
                }
        }
    }

    // ---- epilogue ----
    const float* bb = bias + (size_t)e * NFULL;
#pragma unroll
    for (int t = 0; t < 4; t++) {
#pragma unroll
        for (int n = 0; n < 4; n++) {
            int row = m0 + wm + t * 16 + (lane >> 2);
            int col = n0 + wn + n * 8 + ((lane & 3) << 1);
            float b0v = bb[col], b1v = bb[col + 1];
#pragma unroll
            for (int half = 0; half < 2; half++) {
                int r = row + half * 8;
                if (r < cnt) {
                    float v0 = C[t][n][2 * half + 0] + b0v;
                    float v1 = C[t][n][2 * half + 1] + b1v;
                    size_t o = (size_t)(base + r) * NFULL + col;
                    if (GELUQ) {
                        float gg0 = gelu_exact(v0), gg1 = gelu_exact(v1);
                        __half h0, h1, l0, l1;
                        split_h(gg0, h0, l0); split_h(gg1, h1, l1);
                        *(__half2*)(g_hh + o) = __halves2half2(h0, h1);
                        *(__half2*)(g_hl + o) = __halves2half2(l0, l1);
                    } else {
                        *(float2*)(g_y + o) = make_float2(v0, v1);
                    }
                }
            }
        }
    }
}

// ---------------- 7) combine ----------------
__global__ void combine_kernel(float* __restrict__ out) {
    int i = blockIdx.x * blockDim.x + threadIdx.x;
    if (i >= NTOK * (D / 4)) return;
    int t = i >> 7;
    int seg = (i & 127) << 2;
    int s0 = g_slot[2 * t], s1 = g_slot[2 * t + 1];
    float w0 = g_wt[s0], w1 = g_wt[s1];
    float4 a = *(const float4*)(g_y + (size_t)s0 * D + seg);
    float4 b = *(const float4*)(g_y + (size_t)s1 * D + seg);
    float4 o;
    o.x = w0 * a.x + w1 * b.x;
    o.y = w0 * a.y + w1 * b.y;
    o.z = w0 * a.z + w1 * b.z;
    o.w = w0 * a.w + w1 * b.w;
    *(float4*)(out + (size_t)t * D + seg) = o;
}

// ---------------- host ----------------
extern "C" void kernel_launch(void* const* d_in, const int* in_sizes, int n_in,
                              void* d_out, int out_size) {
    const float* x      = (const float*)d_in[0];
    const float* gate_w = (const float*)d_in[1];
    const float* gate_b = (const float*)d_in[2];
    const float* w1     = (const float*)d_in[3];
    const float* b1     = (const float*)d_in[4];
    const float* w2     = (const float*)d_in[5];
    const float* b2     = (const float*)d_in[6];

    float* out   = (float*)d_out;
    float* probs = out + (size_t)NTOK * D;

    cudaFuncSetAttribute(moe_gemm<512, 1024, true, true>,
                         cudaFuncAttributeMaxDynamicSharedMemorySize, SMEM_GEMM);
    cudaFuncSetAttribute(moe_gemm<1024, 512, false, false>,
                         cudaFuncAttributeMaxDynamicSharedMemorySize, SMEM_GEMM);

    router_kernel<<<NTOK / 8, dim3(32, 8)>>>(x, gate_w, gate_b, probs);
    tilecnt_kernel<<<NTILE, 256>>>();
    offsets_kernel<<<1, 32>>>();
    scatter_kernel<<<NTILE, 256>>>();

    conv_x_kernel<<<(NTOK * D / 4 + 255) / 256, 256>>>(x);
    conv_w1_kernel<<<dim3(HH / 32, D / 32, E), dim3(32, 8)>>>(w1);
    conv_w2_kernel<<<dim3(D / 32, HH / 32, E), dim3(32, 8)>>>(w2);

    moe_gemm<512, 1024, true, true><<<dim3(HH / 128, AMAX / 128, E), 256, SMEM_GEMM>>>(b1);
    moe_gemm<1024, 512, false, false><<<dim3(D / 128, AMAX / 128, E), 256, SMEM_GEMM>>>(b2);

    combine_kernel<<<(NTOK * (D / 4) + 255) / 256, 256>>>(out);
}

// round 5
// speedup vs baseline: 1.4327x; 1.4327x over previous
#include <cuda_runtime.h>
#include <cuda_fp16.h>
#include <math.h>
#include <stdint.h>

// ---------------- problem constants ----------------
constexpr int E    = 8;
constexpr int D    = 512;
constexpr int HH   = 1024;
constexpr int NTOK = 8192;
constexpr int AMAX = NTOK * 2;     // exactly 2 assignments per token
constexpr int NTILE = 32;          // routing tiles of 256 tokens

// ---------------- device scratch (static; no allocation) ----------------
__device__ __half g_xh[(size_t)NTOK * D];
__device__ __half g_xl[(size_t)NTOK * D];
__device__ __half g_w1h[(size_t)E * HH * D];   // [E][H][D]  (w1 transposed, fp16)
__device__ __half g_w2h[(size_t)E * D * HH];   // [E][D][H]  (w2 transposed, fp16)
__device__ __half g_hh[(size_t)AMAX * HH];     // gelu(h) hi
__device__ __half g_hl[(size_t)AMAX * HH];     // gelu(h) lo
__device__ float  g_y[(size_t)AMAX * D];

__device__ int   g_tok[AMAX];
__device__ float g_wt[AMAX];
__device__ int   g_slot[NTOK * 2];
__device__ int   g_topi[NTOK * 2];
__device__ float g_topw[NTOK * 2];
__device__ int   g_count[E];
__device__ int   g_offs[E + 1];
__device__ int   g_tilecnt[NTILE][E];
__device__ int   g_tileoff[NTILE][E];

// ---------------- PTX helpers (baseline sm_80; no arch-'a' features) -------
__device__ __forceinline__ uint32_t smem_u32(const void* p) {
    uint32_t a;
    asm("{ .reg .u64 t; cvta.to.shared.u64 t, %1; cvt.u32.u64 %0, t; }" : "=r"(a) : "l"(p));
    return a;
}
__device__ __forceinline__ void cp_async16(uint32_t dst, const void* src) {
    asm volatile("cp.async.cg.shared.global [%0], [%1], 16;" :: "r"(dst), "l"(src));
}
#define CP_COMMIT() asm volatile("cp.async.commit_group;" ::: "memory")
#define CP_WAIT(n)  asm volatile("cp.async.wait_group %0;" :: "n"(n) : "memory")

__device__ __forceinline__ void ldmatrix_x4(uint32_t* f, uint32_t addr) {
    asm volatile("ldmatrix.sync.aligned.m8n8.x4.shared.b16 {%0,%1,%2,%3}, [%4];"
                 : "=r"(f[0]), "=r"(f[1]), "=r"(f[2]), "=r"(f[3]) : "r"(addr));
}
__device__ __forceinline__ void mma_16816(float* c, const uint32_t* a, const uint32_t* b) {
    asm volatile("mma.sync.aligned.m16n8k16.row.col.f32.f16.f16.f32 "
                 "{%0,%1,%2,%3}, {%4,%5,%6,%7}, {%8,%9}, {%0,%1,%2,%3};"
                 : "+f"(c[0]), "+f"(c[1]), "+f"(c[2]), "+f"(c[3])
                 : "r"(a[0]), "r"(a[1]), "r"(a[2]), "r"(a[3]), "r"(b[0]), "r"(b[1]));
}

__device__ __forceinline__ float gelu_exact(float v) {
    return 0.5f * v * (1.0f + erff(v * 0.70710678118654752f));
}
__device__ __forceinline__ void split_h(float v, __half& h, __half& l) {
    h = __float2half_rn(v);
    l = __float2half_rn(v - __half2float(h));
}

// ---------------- 1) router ----------------
__global__ void router_kernel(const float* __restrict__ x,
                              const float* __restrict__ gw,
                              const float* __restrict__ gb,
                              float* __restrict__ probs) {
    int t = blockIdx.x * blockDim.y + threadIdx.y;
    if (t >= NTOK) return;
    int lane = threadIdx.x;
    float acc[E];
#pragma unroll
    for (int e = 0; e < E; e++) acc[e] = 0.0f;
    const float* xr = x + (size_t)t * D;
    for (int d = lane; d < D; d += 32) {
        float xv = xr[d];
        const float* g = gw + d * E;
#pragma unroll
        for (int e = 0; e < E; e++) acc[e] += xv * g[e];
    }
#pragma unroll
    for (int e = 0; e < E; e++)
#pragma unroll
        for (int off = 16; off > 0; off >>= 1)
            acc[e] += __shfl_xor_sync(0xffffffffu, acc[e], off);
    if (lane == 0) {
        float p[E]; float mx = -1e30f;
#pragma unroll
        for (int e = 0; e < E; e++) { p[e] = acc[e] + gb[e]; mx = fmaxf(mx, p[e]); }
        float s = 0.0f;
#pragma unroll
        for (int e = 0; e < E; e++) { p[e] = expf(p[e] - mx); s += p[e]; }
        float inv = 1.0f / s;
#pragma unroll
        for (int e = 0; e < E; e++) { p[e] *= inv; probs[(size_t)t * E + e] = p[e]; }
        int i0 = 0; float v0 = p[0];
#pragma unroll
        for (int e = 1; e < E; e++) if (p[e] > v0) { v0 = p[e]; i0 = e; }
        int i1 = -1; float v1 = -1.0f;
#pragma unroll
        for (int e = 0; e < E; e++) if (e != i0 && p[e] > v1) { v1 = p[e]; i1 = e; }
        float ws = 1.0f / (v0 + v1);
        g_topi[2 * t] = i0; g_topi[2 * t + 1] = i1;
        g_topw[2 * t] = v0 * ws; g_topw[2 * t + 1] = v1 * ws;
    }
}

// ---------------- 2) per-tile counts ----------------
__global__ void tilecnt_kernel() {
    __shared__ int cnt[E];
    int t = blockIdx.x * 256 + threadIdx.x;
    if (threadIdx.x < E) cnt[threadIdx.x] = 0;
    __syncthreads();
    int e0 = g_topi[2 * t], e1 = g_topi[2 * t + 1];
    int lane = threadIdx.x & 31;
#pragma unroll
    for (int e = 0; e < E; e++) {
        unsigned m = __ballot_sync(0xffffffffu, e0 == e || e1 == e);
        if (lane == 0) atomicAdd(&cnt[e], __popc(m));
    }
    __syncthreads();
    if (threadIdx.x < E) g_tilecnt[blockIdx.x][threadIdx.x] = cnt[threadIdx.x];
}

// ---------------- 3) offsets ----------------
__global__ void offsets_kernel() {
    if (threadIdx.x != 0) return;
    int tot[E];
    for (int e = 0; e < E; e++) { int s = 0; for (int b = 0; b < NTILE; b++) s += g_tilecnt[b][e]; tot[e] = s; }
    int s = 0;
    for (int e = 0; e < E; e++) { g_offs[e] = s; g_count[e] = tot[e]; s += tot[e]; }
    g_offs[E] = s;
    for (int e = 0; e < E; e++) { int r = g_offs[e]; for (int b = 0; b < NTILE; b++) { g_tileoff[b][e] = r; r += g_tilecnt[b][e]; } }
}

// ---------------- 4) deterministic scatter ----------------
__global__ void scatter_kernel() {
    __shared__ int wcnt[8][E];
    int t = blockIdx.x * 256 + threadIdx.x;
    int lane = threadIdx.x & 31, w = threadIdx.x >> 5;
    int e0 = g_topi[2 * t], e1 = g_topi[2 * t + 1];
    unsigned mask[E];
#pragma unroll
    for (int e = 0; e < E; e++) {
        mask[e] = __ballot_sync(0xffffffffu, e0 == e || e1 == e);
        if (lane == 0) wcnt[w][e] = __popc(mask[e]);
    }
    __syncthreads();
#pragma unroll
    for (int e = 0; e < E; e++) {
        if (e == e0 || e == e1) {
            int pre = 0;
            for (int ww = 0; ww < w; ww++) pre += wcnt[ww][e];
            int pos = g_tileoff[blockIdx.x][e] + pre + __popc(mask[e] & ((1u << lane) - 1));
            int which = (e == e0) ? 0 : 1;
            g_tok[pos] = t;
            g_wt[pos] = g_topw[2 * t + which];
            g_slot[2 * t + which] = pos;
        }
    }
}

// ---------------- 5) conversions ----------------
__global__ void conv_x_kernel(const float* __restrict__ x) {
    int i = blockIdx.x * blockDim.x + threadIdx.x;     // float4 index
    if (i >= NTOK * D / 4) return;
    float4 v = ((const float4*)x)[i];
    __half h0, h1, h2, h3, l0, l1, l2, l3;
    split_h(v.x, h0, l0); split_h(v.y, h1, l1);
    split_h(v.z, h2, l2); split_h(v.w, h3, l3);
    __half2* ph = (__half2*)g_xh;
    __half2* pl = (__half2*)g_xl;
    ph[2 * i]     = __halves2half2(h0, h1);
    ph[2 * i + 1] = __halves2half2(h2, h3);
    pl[2 * i]     = __halves2half2(l0, l1);
    pl[2 * i + 1] = __halves2half2(l2, l3);
}

// transpose w1[e][d][h] -> g_w1h[e][h][d] (fp16)
__global__ void conv_w1_kernel(const float* __restrict__ w1) {
    __shared__ float t[32][33];
    int h0 = blockIdx.x * 32, d0 = blockIdx.y * 32, e = blockIdx.z;
#pragma unroll
    for (int i = 0; i < 4; i++) {
        int r = threadIdx.y + 8 * i;
        t[r][threadIdx.x] = w1[((size_t)e * D + d0 + r) * HH + h0 + threadIdx.x];
    }
    __syncthreads();
#pragma unroll
    for (int i = 0; i < 4; i++) {
        int r = threadIdx.y + 8 * i;
        size_t o = ((size_t)e * HH + h0 + r) * D + d0 + threadIdx.x;
        g_w1h[o] = __float2half_rn(t[threadIdx.x][r]);
    }
}
// transpose w2[e][h][d] -> g_w2h[e][d][h] (fp16)
__global__ void conv_w2_kernel(const float* __restrict__ w2) {
    __shared__ float t[32][33];
    int d0 = blockIdx.x * 32, h0 = blockIdx.y * 32, e = blockIdx.z;
#pragma unroll
    for (int i = 0; i < 4; i++) {
        int r = threadIdx.y + 8 * i;
        t[r][threadIdx.x] = w2[((size_t)e * HH + h0 + r) * D + d0 + threadIdx.x];
    }
    __syncthreads();
#pragma unroll
    for (int i = 0; i < 4; i++) {
        int r = threadIdx.y + 8 * i;
        size_t o = ((size_t)e * D + d0 + r) * HH + h0 + threadIdx.x;
        g_w2h[o] = __float2half_rn(t[threadIdx.x][r]);
    }
}

// ---------------- 6) HMMA grouped GEMM ----------------
// CTA tile 128x128, BK=32 halves, 4-stage cp.async pipeline, 1 sync/iter.
// smem per matrix: 128 rows x 40 halves (stride 80B). Ah|Al|B per stage.
constexpr int MAT_B   = 128 * 80;            // 10240 B
constexpr int STAGE_B = 3 * MAT_B;           // 30720 B
constexpr int SMEM_GEMM = 1024 + 4 * STAGE_B; // 123904 B

template <int KTOT, int NFULL, bool GATHER, bool GELUQ>
__global__ __launch_bounds__(256, 1) void moe_gemm(const float* __restrict__ bias) {
    constexpr int NC = KTOT / 32;
    const int e = blockIdx.z;
    const int cnt = g_count[e];
    const int m0 = blockIdx.y * 128;
    if (m0 >= cnt) return;
    const int base = g_offs[e];
    const int n0 = blockIdx.x * 128;

    extern __shared__ char smem[];
    const uint32_t sb = smem_u32(smem);
    int* s_tok = (int*)smem;               // 128 ints
    const uint32_t TILE = sb + 1024;

    const int tid = threadIdx.x;
    const int lane = tid & 31;
    const int wid = tid >> 5;
    const int wm = (wid >> 2) * 64;        // warp m offset (0,64)
    const int wn = (wid & 3) * 32;         // warp n offset (0..96)

    const __half* Ah = GATHER ? g_xh : g_hh;
    const __half* Al = GATHER ? g_xl : g_hl;
    const __half* Bp = GELUQ ? g_w1h : g_w2h;

    if (tid < 128) {
        int r = base + m0 + tid; if (r > AMAX - 1) r = AMAX - 1;
        s_tok[tid] = GATHER ? g_tok[r] : r;
    }
    __syncthreads();

    // loader: 1536 16B-chunks / 256 threads = 6 per thread
    const __half* srcp[6];
    uint32_t dstoff[6];
#pragma unroll
    for (int i = 0; i < 6; i++) {
        int g = i * 256 + tid;
        int mat = g >> 9, idx = g & 511, row = idx >> 2, seg = idx & 3;
        const __half* sp;
        if (mat < 2) {
            sp = (mat == 0 ? Ah : Al) + (size_t)s_tok[row] * KTOT + seg * 8;
        } else {
            sp = Bp + ((size_t)e * NFULL + n0 + row) * KTOT + seg * 8;
        }
        srcp[i] = sp;
        dstoff[i] = (uint32_t)(mat * MAT_B + row * 80 + seg * 16);
    }

    auto load_stage = [&](int c) {
        uint32_t stg = TILE + (c & 3) * STAGE_B;
        int k0 = c * 32;
#pragma unroll
        for (int i = 0; i < 6; i++) cp_async16(stg + dstoff[i], srcp[i] + k0);
    };

    float C[4][4][4];
#pragma unroll
    for (int t = 0; t < 4; t++)
#pragma unroll
        for (int n = 0; n < 4; n++)
#pragma unroll
            for (int j = 0; j < 4; j++) C[t][n][j] = 0.0f;

    load_stage(0); CP_COMMIT();
    load_stage(1); CP_COMMIT();
    load_stage(2); CP_COMMIT();

    // precomputed fragment address components
    const uint32_t a_row_off = (uint32_t)((wm + (lane & 15)) * 80 + ((lane >> 4) << 4));
    const int bq = lane >> 3, br = lane & 7;
    const uint32_t b_row_off = (uint32_t)(2 * MAT_B + (wn + ((bq >> 1) << 3) + br) * 80 + ((bq & 1) << 4));

    for (int c = 0; c < NC; c++) {
        CP_WAIT(2);
        __syncthreads();
        if (c + 3 < NC) load_stage(c + 3);
        CP_COMMIT();

        const uint32_t stg = TILE + (c & 3) * STAGE_B;
#pragma unroll
        for (int s = 0; s < 2; s++) {           // two K=16 slices
            uint32_t ah[4][4], al[4][4];
#pragma unroll
            for (int t = 0; t < 4; t++) {
                uint32_t ra = stg + a_row_off + t * (16 * 80) + s * 32;
                ldmatrix_x4(ah[t], ra);
                ldmatrix_x4(al[t], ra + MAT_B);
            }
            uint32_t bf[4][2];
#pragma unroll
            for (int nb = 0; nb < 2; nb++) {
                uint32_t rb = stg + b_row_off + nb * (16 * 80) + s * 32;
                uint32_t f[4];
                ldmatrix_x4(f, rb);
                bf[nb * 2][0] = f[0]; bf[nb * 2][1] = f[1];
                bf[nb * 2 + 1][0] = f[2]; bf[nb * 2 + 1][1] = f[3];
            }
#pragma unroll
            for (int t = 0; t < 4; t++)
#pragma unroll
                for (int n = 0; n < 4; n++) {
                    mma_16816(C[t][n], ah[t], bf[n]);
                    mma_16816(C[t][n], al[t], bf[n]);
                }
        }
    }

    // ---- epilogue ----
    const float* bb = bias + (size_t)e * NFULL;
#pragma unroll
    for (int t = 0; t < 4; t++) {
#pragma unroll
        for (int n = 0; n < 4; n++) {
            int row = m0 + wm + t * 16 + (lane >> 2);
            int col = n0 + wn + n * 8 + ((lane & 3) << 1);
            float b0v = bb[col], b1v = bb[col + 1];
#pragma unroll
            for (int half = 0; half < 2; half++) {
                int r = row + half * 8;
                if (r < cnt) {
                    float v0 = C[t][n][2 * half + 0] + b0v;
                    float v1 = C[t][n][2 * half + 1] + b1v;
                    size_t o = (size_t)(base + r) * NFULL + col;
                    if (GELUQ) {
                        float gg0 = gelu_exact(v0), gg1 = gelu_exact(v1);
                        __half h0, h1, l0, l1;
                        split_h(gg0, h0, l0); split_h(gg1, h1, l1);
                        *(__half2*)(g_hh + o) = __halves2half2(h0, h1);
                        *(__half2*)(g_hl + o) = __halves2half2(l0, l1);
                    } else {
                        *(float2*)(g_y + o) = make_float2(v0, v1);
                    }
                }
            }
        }
    }
}

// ---------------- 7) combine ----------------
__global__ void combine_kernel(float* __restrict__ out) {
    int i = blockIdx.x * blockDim.x + threadIdx.x;
    if (i >= NTOK * (D / 4)) return;
    int t = i >> 7;
    int seg = (i & 127) << 2;
    int s0 = g_slot[2 * t], s1 = g_slot[2 * t + 1];
    float w0 = g_wt[s0], w1 = g_wt[s1];
    float4 a = *(const float4*)(g_y + (size_t)s0 * D + seg);
    float4 b = *(const float4*)(g_y + (size_t)s1 * D + seg);
    float4 o;
    o.x = w0 * a.x + w1 * b.x;
    o.y = w0 * a.y + w1 * b.y;
    o.z = w0 * a.z + w1 * b.z;
    o.w = w0 * a.w + w1 * b.w;
    *(float4*)(out + (size_t)t * D + seg) = o;
}

// ---------------- host ----------------
extern "C" void kernel_launch(void* const* d_in, const int* in_sizes, int n_in,
                              void* d_out, int out_size) {
    const float* x      = (const float*)d_in[0];
    const float* gate_w = (const float*)d_in[1];
    const float* gate_b = (const float*)d_in[2];
    const float* w1     = (const float*)d_in[3];
    const float* b1     = (const float*)d_in[4];
    const float* w2     = (const float*)d_in[5];
    const float* b2     = (const float*)d_in[6];

    float* out   = (float*)d_out;
    float* probs = out + (size_t)NTOK * D;

    cudaFuncSetAttribute(moe_gemm<512, 1024, true, true>,
                         cudaFuncAttributeMaxDynamicSharedMemorySize, SMEM_GEMM);
    cudaFuncSetAttribute(moe_gemm<1024, 512, false, false>,
                         cudaFuncAttributeMaxDynamicSharedMemorySize, SMEM_GEMM);

    router_kernel<<<NTOK / 8, dim3(32, 8)>>>(x, gate_w, gate_b, probs);
    tilecnt_kernel<<<NTILE, 256>>>();
    offsets_kernel<<<1, 32>>>();
    scatter_kernel<<<NTILE, 256>>>();

    conv_x_kernel<<<(NTOK * D / 4 + 255) / 256, 256>>>(x);
    conv_w1_kernel<<<dim3(HH / 32, D / 32, E), dim3(32, 8)>>>(w1);
    conv_w2_kernel<<<dim3(D / 32, HH / 32, E), dim3(32, 8)>>>(w2);

    // cnt_e <= NTOK, so 64 m-tiles per expert suffice
    moe_gemm<512, 1024, true, true><<<dim3(HH / 128, NTOK / 128, E), 256, SMEM_GEMM>>>(b1);
    moe_gemm<1024, 512, false, false><<<dim3(D / 128, NTOK / 128, E), 256, SMEM_GEMM>>>(b2);

    combine_kernel<<<(NTOK * (D / 4) + 255) / 256, 256>>>(out);
}

// round 6
// speedup vs baseline: 1.9192x; 1.3396x over previous
#include <cuda_runtime.h>
#include <cuda_fp16.h>
#include <math.h>
#include <stdint.h>

// ---------------- problem constants ----------------
constexpr int E    = 8;
constexpr int D    = 512;
constexpr int HH   = 1024;
constexpr int NTOK = 8192;
constexpr int AMAX = NTOK * 2;     // exactly 2 assignments per token
constexpr int NTILE = 32;          // routing tiles of 256 tokens

// ---------------- device scratch (static; no allocation) ----------------
__device__ __half g_xh[(size_t)NTOK * D];      // x in fp16
__device__ __half g_w1h[(size_t)E * HH * D];   // [E][H][D]  (w1 transposed, fp16)
__device__ __half g_w2h[(size_t)E * D * HH];   // [E][D][H]  (w2 transposed, fp16)
__device__ __half g_hh[(size_t)AMAX * HH];     // gelu(h) fp16
__device__ float  g_y[(size_t)AMAX * D];

__device__ int   g_tok[AMAX];
__device__ float g_wt[AMAX];
__device__ int   g_slot[NTOK * 2];
__device__ int   g_topi[NTOK * 2];
__device__ float g_topw[NTOK * 2];
__device__ int   g_count[E];
__device__ int   g_offs[E + 1];
__device__ int   g_tilecnt[NTILE][E];
__device__ int   g_tileoff[NTILE][E];

// ---------------- PTX helpers (baseline sm_80; no arch-'a' features) -------
__device__ __forceinline__ uint32_t smem_u32(const void* p) {
    uint32_t a;
    asm("{ .reg .u64 t; cvta.to.shared.u64 t, %1; cvt.u32.u64 %0, t; }" : "=r"(a) : "l"(p));
    return a;
}
__device__ __forceinline__ void cp_async16(uint32_t dst, const void* src) {
    asm volatile("cp.async.cg.shared.global [%0], [%1], 16;" :: "r"(dst), "l"(src));
}
#define CP_COMMIT() asm volatile("cp.async.commit_group;" ::: "memory")
#define CP_WAIT(n)  asm volatile("cp.async.wait_group %0;" :: "n"(n) : "memory")

__device__ __forceinline__ void ldmatrix_x4(uint32_t* f, uint32_t addr) {
    asm volatile("ldmatrix.sync.aligned.m8n8.x4.shared.b16 {%0,%1,%2,%3}, [%4];"
                 : "=r"(f[0]), "=r"(f[1]), "=r"(f[2]), "=r"(f[3]) : "r"(addr));
}
__device__ __forceinline__ void mma_16816(float* c, const uint32_t* a, const uint32_t* b) {
    asm volatile("mma.sync.aligned.m16n8k16.row.col.f32.f16.f16.f32 "
                 "{%0,%1,%2,%3}, {%4,%5,%6,%7}, {%8,%9}, {%0,%1,%2,%3};"
                 : "+f"(c[0]), "+f"(c[1]), "+f"(c[2]), "+f"(c[3])
                 : "r"(a[0]), "r"(a[1]), "r"(a[2]), "r"(a[3]), "r"(b[0]), "r"(b[1]));
}

__device__ __forceinline__ float gelu_exact(float v) {
    return 0.5f * v * (1.0f + erff(v * 0.70710678118654752f));
}

// ---------------- 1) router (+ fused x -> fp16 conversion) ----------------
__global__ void router_kernel(const float* __restrict__ x,
                              const float* __restrict__ gw,
                              const float* __restrict__ gb,
                              float* __restrict__ probs) {
    int t = blockIdx.x * blockDim.y + threadIdx.y;
    if (t >= NTOK) return;
    int lane = threadIdx.x;
    float acc[E];
#pragma unroll
    for (int e = 0; e < E; e++) acc[e] = 0.0f;
    const float* xr = x + (size_t)t * D;
    __half* xo = g_xh + (size_t)t * D;
    for (int d = lane; d < D; d += 32) {
        float xv = xr[d];
        xo[d] = __float2half_rn(xv);             // fused conversion
        const float* g = gw + d * E;
#pragma unroll
        for (int e = 0; e < E; e++) acc[e] += xv * g[e];
    }
#pragma unroll
    for (int e = 0; e < E; e++)
#pragma unroll
        for (int off = 16; off > 0; off >>= 1)
            acc[e] += __shfl_xor_sync(0xffffffffu, acc[e], off);
    if (lane == 0) {
        float p[E]; float mx = -1e30f;
#pragma unroll
        for (int e = 0; e < E; e++) { p[e] = acc[e] + gb[e]; mx = fmaxf(mx, p[e]); }
        float s = 0.0f;
#pragma unroll
        for (int e = 0; e < E; e++) { p[e] = expf(p[e] - mx); s += p[e]; }
        float inv = 1.0f / s;
#pragma unroll
        for (int e = 0; e < E; e++) { p[e] *= inv; probs[(size_t)t * E + e] = p[e]; }
        int i0 = 0; float v0 = p[0];
#pragma unroll
        for (int e = 1; e < E; e++) if (p[e] > v0) { v0 = p[e]; i0 = e; }
        int i1 = -1; float v1 = -1.0f;
#pragma unroll
        for (int e = 0; e < E; e++) if (e != i0 && p[e] > v1) { v1 = p[e]; i1 = e; }
        float ws = 1.0f / (v0 + v1);
        g_topi[2 * t] = i0; g_topi[2 * t + 1] = i1;
        g_topw[2 * t] = v0 * ws; g_topw[2 * t + 1] = v1 * ws;
    }
}

// ---------------- 2) per-tile counts ----------------
__global__ void tilecnt_kernel() {
    __shared__ int cnt[E];
    int t = blockIdx.x * 256 + threadIdx.x;
    if (threadIdx.x < E) cnt[threadIdx.x] = 0;
    __syncthreads();
    int e0 = g_topi[2 * t], e1 = g_topi[2 * t + 1];
    int lane = threadIdx.x & 31;
#pragma unroll
    for (int e = 0; e < E; e++) {
        unsigned m = __ballot_sync(0xffffffffu, e0 == e || e1 == e);
        if (lane == 0) atomicAdd(&cnt[e], __popc(m));
    }
    __syncthreads();
    if (threadIdx.x < E) g_tilecnt[blockIdx.x][threadIdx.x] = cnt[threadIdx.x];
}

// ---------------- 3) offsets ----------------
__global__ void offsets_kernel() {
    if (threadIdx.x != 0) return;
    int tot[E];
    for (int e = 0; e < E; e++) { int s = 0; for (int b = 0; b < NTILE; b++) s += g_tilecnt[b][e]; tot[e] = s; }
    int s = 0;
    for (int e = 0; e < E; e++) { g_offs[e] = s; g_count[e] = tot[e]; s += tot[e]; }
    g_offs[E] = s;
    for (int e = 0; e < E; e++) { int r = g_offs[e]; for (int b = 0; b < NTILE; b++) { g_tileoff[b][e] = r; r += g_tilecnt[b][e]; } }
}

// ---------------- 4) deterministic scatter ----------------
__global__ void scatter_kernel() {
    __shared__ int wcnt[8][E];
    int t = blockIdx.x * 256 + threadIdx.x;
    int lane = threadIdx.x & 31, w = threadIdx.x >> 5;
    int e0 = g_topi[2 * t], e1 = g_topi[2 * t + 1];
    unsigned mask[E];
#pragma unroll
    for (int e = 0; e < E; e++) {
        mask[e] = __ballot_sync(0xffffffffu, e0 == e || e1 == e);
        if (lane == 0) wcnt[w][e] = __popc(mask[e]);
    }
    __syncthreads();
#pragma unroll
    for (int e = 0; e < E; e++) {
        if (e == e0 || e == e1) {
            int pre = 0;
            for (int ww = 0; ww < w; ww++) pre += wcnt[ww][e];
            int pos = g_tileoff[blockIdx.x][e] + pre + __popc(mask[e] & ((1u << lane) - 1));
            int which = (e == e0) ? 0 : 1;
            g_tok[pos] = t;
            g_wt[pos] = g_topw[2 * t + which];
            g_slot[2 * t + which] = pos;
        }
    }
}

// ---------------- 5) weight conversions (transpose + fp16) ----------------
__global__ void conv_w1_kernel(const float* __restrict__ w1) {
    __shared__ float t[32][33];
    int h0 = blockIdx.x * 32, d0 = blockIdx.y * 32, e = blockIdx.z;
#pragma unroll
    for (int i = 0; i < 4; i++) {
        int r = threadIdx.y + 8 * i;
        t[r][threadIdx.x] = w1[((size_t)e * D + d0 + r) * HH + h0 + threadIdx.x];
    }
    __syncthreads();
#pragma unroll
    for (int i = 0; i < 4; i++) {
        int r = threadIdx.y + 8 * i;
        size_t o = ((size_t)e * HH + h0 + r) * D + d0 + threadIdx.x;
        g_w1h[o] = __float2half_rn(t[threadIdx.x][r]);
    }
}
__global__ void conv_w2_kernel(const float* __restrict__ w2) {
    __shared__ float t[32][33];
    int d0 = blockIdx.x * 32, h0 = blockIdx.y * 32, e = blockIdx.z;
#pragma unroll
    for (int i = 0; i < 4; i++) {
        int r = threadIdx.y + 8 * i;
        t[r][threadIdx.x] = w2[((size_t)e * HH + h0 + r) * D + d0 + threadIdx.x];
    }
    __syncthreads();
#pragma unroll
    for (int i = 0; i < 4; i++) {
        int r = threadIdx.y + 8 * i;
        size_t o = ((size_t)e * D + d0 + r) * HH + h0 + threadIdx.x;
        g_w2h[o] = __float2half_rn(t[threadIdx.x][r]);
    }
}

// ---------------- 6) HMMA grouped GEMM ----------------
// CTA tile 128x128, BK=32, 5-stage cp.async pipeline, 1 sync/iter.
// smem per matrix: 128 rows x 40 halves (stride 80B). A|B per stage.
constexpr int MAT_B   = 128 * 80;             // 10240 B
constexpr int STAGE_B = 2 * MAT_B;            // 20480 B
constexpr int NSTAGE  = 5;
constexpr int SMEM_GEMM = 1024 + NSTAGE * STAGE_B; // 103424 B

template <int KTOT, int NFULL, bool GATHER, bool GELUQ>
__global__ __launch_bounds__(256, 1) void moe_gemm(const float* __restrict__ bias) {
    constexpr int NC = KTOT / 32;
    const int e = blockIdx.z;
    const int cnt = g_count[e];
    const int m0 = blockIdx.y * 128;
    if (m0 >= cnt) return;
    const int base = g_offs[e];
    const int n0 = blockIdx.x * 128;

    extern __shared__ char smem[];
    const uint32_t sb = smem_u32(smem);
    int* s_tok = (int*)smem;               // 128 ints
    const uint32_t TILE = sb + 1024;

    const int tid = threadIdx.x;
    const int lane = tid & 31;
    const int wid = tid >> 5;
    const int wm = (wid >> 2) * 64;        // warp m offset (0,64)
    const int wn = (wid & 3) * 32;         // warp n offset (0..96)

    const __half* Ap = GATHER ? g_xh : g_hh;
    const __half* Bp = GELUQ ? g_w1h : g_w2h;

    if (tid < 128) {
        int r = base + m0 + tid; if (r > AMAX - 1) r = AMAX - 1;
        s_tok[tid] = GATHER ? g_tok[r] : r;
    }
    __syncthreads();

    // loader: 1024 16B-chunks / 256 threads = 4 per thread
    const __half* srcp[4];
    uint32_t dstoff[4];
#pragma unroll
    for (int i = 0; i < 4; i++) {
        int g = i * 256 + tid;
        int mat = g >> 9, idx = g & 511, row = idx >> 2, seg = idx & 3;
        const __half* sp;
        if (mat == 0) {
            sp = Ap + (size_t)s_tok[row] * KTOT + seg * 8;
        } else {
            sp = Bp + ((size_t)e * NFULL + n0 + row) * KTOT + seg * 8;
        }
        srcp[i] = sp;
        dstoff[i] = (uint32_t)(mat * MAT_B + row * 80 + seg * 16);
    }

    auto load_stage = [&](int c) {
        uint32_t stg = TILE + (c % NSTAGE) * STAGE_B;
        int k0 = c * 32;
#pragma unroll
        for (int i = 0; i < 4; i++) cp_async16(stg + dstoff[i], srcp[i] + k0);
    };

    float C[4][4][4];
#pragma unroll
    for (int t = 0; t < 4; t++)
#pragma unroll
        for (int n = 0; n < 4; n++)
#pragma unroll
            for (int j = 0; j < 4; j++) C[t][n][j] = 0.0f;

    load_stage(0); CP_COMMIT();
    load_stage(1); CP_COMMIT();
    load_stage(2); CP_COMMIT();
    load_stage(3); CP_COMMIT();

    // fragment address components
    const uint32_t a_row_off = (uint32_t)((wm + (lane & 15)) * 80 + ((lane >> 4) << 4));
    const int bq = lane >> 3, br = lane & 7;
    const uint32_t b_row_off = (uint32_t)(MAT_B + (wn + ((bq >> 1) << 3) + br) * 80 + ((bq & 1) << 4));

    for (int c = 0; c < NC; c++) {
        CP_WAIT(3);
        __syncthreads();
        if (c + 4 < NC) load_stage(c + 4);
        CP_COMMIT();

        const uint32_t stg = TILE + (c % NSTAGE) * STAGE_B;
#pragma unroll
        for (int s = 0; s < 2; s++) {           // two K=16 slices
            uint32_t af[4][4];
#pragma unroll
            for (int t = 0; t < 4; t++) {
                uint32_t ra = stg + a_row_off + t * (16 * 80) + s * 32;
                ldmatrix_x4(af[t], ra);
            }
            uint32_t bf[4][2];
#pragma unroll
            for (int nb = 0; nb < 2; nb++) {
                uint32_t rb = stg + b_row_off + nb * (16 * 80) + s * 32;
                uint32_t f[4];
                ldmatrix_x4(f, rb);
                bf[nb * 2][0] = f[0]; bf[nb * 2][1] = f[1];
                bf[nb * 2 + 1][0] = f[2]; bf[nb * 2 + 1][1] = f[3];
            }
#pragma unroll
            for (int t = 0; t < 4; t++)
#pragma unroll
                for (int n = 0; n < 4; n++)
                    mma_16816(C[t][n], af[t], bf[n]);
        }
    }

    // ---- epilogue ----
    const float* bb = bias + (size_t)e * NFULL;
#pragma unroll
    for (int t = 0; t < 4; t++) {
#pragma unroll
        for (int n = 0; n < 4; n++) {
            int row = m0 + wm + t * 16 + (lane >> 2);
            int col = n0 + wn + n * 8 + ((lane & 3) << 1);
            float b0v = bb[col], b1v = bb[col + 1];
#pragma unroll
            for (int half = 0; half < 2; half++) {
                int r = row + half * 8;
                if (r < cnt) {
                    float v0 = C[t][n][2 * half + 0] + b0v;
                    float v1 = C[t][n][2 * half + 1] + b1v;
                    size_t o = (size_t)(base + r) * NFULL + col;
                    if (GELUQ) {
                        *(__half2*)(g_hh + o) = __halves2half2(
                            __float2half_rn(gelu_exact(v0)),
                            __float2half_rn(gelu_exact(v1)));
                    } else {
                        *(float2*)(g_y + o) = make_float2(v0, v1);
                    }
                }
            }
        }
    }
}

// ---------------- 7) combine ----------------
__global__ void combine_kernel(float* __restrict__ out) {
    int i = blockIdx.x * blockDim.x + threadIdx.x;
    if (i >= NTOK * (D / 4)) return;
    int t = i >> 7;
    int seg = (i & 127) << 2;
    int s0 = g_slot[2 * t], s1 = g_slot[2 * t + 1];
    float w0 = g_wt[s0], w1 = g_wt[s1];
    float4 a = *(const float4*)(g_y + (size_t)s0 * D + seg);
    float4 b = *(const float4*)(g_y + (size_t)s1 * D + seg);
    float4 o;
    o.x = w0 * a.x + w1 * b.x;
    o.y = w0 * a.y + w1 * b.y;
    o.z = w0 * a.z + w1 * b.z;
    o.w = w0 * a.w + w1 * b.w;
    *(float4*)(out + (size_t)t * D + seg) = o;
}

// ---------------- host ----------------
extern "C" void kernel_launch(void* const* d_in, const int* in_sizes, int n_in,
                              void* d_out, int out_size) {
    const float* x      = (const float*)d_in[0];
    const float* gate_w = (const float*)d_in[1];
    const float* gate_b = (const float*)d_in[2];
    const float* w1     = (const float*)d_in[3];
    const float* b1     = (const float*)d_in[4];
    const float* w2     = (const float*)d_in[5];
    const float* b2     = (const float*)d_in[6];

    float* out   = (float*)d_out;
    float* probs = out + (size_t)NTOK * D;

    cudaFuncSetAttribute(moe_gemm<512, 1024, true, true>,
                         cudaFuncAttributeMaxDynamicSharedMemorySize, SMEM_GEMM);
    cudaFuncSetAttribute(moe_gemm<1024, 512, false, false>,
                         cudaFuncAttributeMaxDynamicSharedMemorySize, SMEM_GEMM);

    router_kernel<<<NTOK / 8, dim3(32, 8)>>>(x, gate_w, gate_b, probs);
    tilecnt_kernel<<<NTILE, 256>>>();
    offsets_kernel<<<1, 32>>>();
    scatter_kernel<<<NTILE, 256>>>();

    conv_w1_kernel<<<dim3(HH / 32, D / 32, E), dim3(32, 8)>>>(w1);
    conv_w2_kernel<<<dim3(D / 32, HH / 32, E), dim3(32, 8)>>>(w2);

    moe_gemm<512, 1024, true, true><<<dim3(HH / 128, NTOK / 128, E), 256, SMEM_GEMM>>>(b1);
    moe_gemm<1024, 512, false, false><<<dim3(D / 128, NTOK / 128, E), 256, SMEM_GEMM>>>(b2);

    combine_kernel<<<(NTOK * (D / 4) + 255) / 256, 256>>>(out);
}

// round 7
// speedup vs baseline: 2.3295x; 1.2138x over previous
#include <cuda_runtime.h>
#include <cuda_fp16.h>
#include <math.h>
#include <stdint.h>

// ---------------- problem constants ----------------
constexpr int E    = 8;
constexpr int D    = 512;
constexpr int HH   = 1024;
constexpr int NTOK = 8192;
constexpr int AMAX = NTOK * 2;     // exactly 2 assignments per token
constexpr int NTILE = 32;          // routing tiles of 256 tokens

// ---------------- device scratch (static; no allocation) ----------------
__device__ __half g_xh[(size_t)NTOK * D];      // x in fp16
__device__ __half g_w1h[(size_t)E * HH * D];   // [E][H][D]  (w1 transposed, fp16)
__device__ __half g_w2h[(size_t)E * D * HH];   // [E][D][H]  (w2 transposed, fp16)
__device__ __half g_hh[(size_t)AMAX * HH];     // gelu(h) fp16

__device__ int   g_tok[AMAX];
__device__ float g_wt[AMAX];
__device__ int   g_topi[NTOK * 2];
__device__ float g_topw[NTOK * 2];
__device__ int   g_count[E];
__device__ int   g_offs[E + 1];
__device__ int   g_tilecnt[NTILE][E];
__device__ int   g_tileoff[NTILE][E];

// ---------------- PTX helpers (baseline sm_80/90; no arch-'a' features) ----
__device__ __forceinline__ uint32_t smem_u32(const void* p) {
    uint32_t a;
    asm("{ .reg .u64 t; cvta.to.shared.u64 t, %1; cvt.u32.u64 %0, t; }" : "=r"(a) : "l"(p));
    return a;
}
__device__ __forceinline__ void cp_async16(uint32_t dst, const void* src) {
    asm volatile("cp.async.cg.shared.global [%0], [%1], 16;" :: "r"(dst), "l"(src));
}
#define CP_COMMIT() asm volatile("cp.async.commit_group;" ::: "memory")
#define CP_WAIT(n)  asm volatile("cp.async.wait_group %0;" :: "n"(n) : "memory")

__device__ __forceinline__ void ldmatrix_x4(uint32_t* f, uint32_t addr) {
    asm volatile("ldmatrix.sync.aligned.m8n8.x4.shared.b16 {%0,%1,%2,%3}, [%4];"
                 : "=r"(f[0]), "=r"(f[1]), "=r"(f[2]), "=r"(f[3]) : "r"(addr));
}
__device__ __forceinline__ void mma_16816(float* c, const uint32_t* a, const uint32_t* b) {
    asm volatile("mma.sync.aligned.m16n8k16.row.col.f32.f16.f16.f32 "
                 "{%0,%1,%2,%3}, {%4,%5,%6,%7}, {%8,%9}, {%0,%1,%2,%3};"
                 : "+f"(c[0]), "+f"(c[1]), "+f"(c[2]), "+f"(c[3])
                 : "r"(a[0]), "r"(a[1]), "r"(a[2]), "r"(a[3]), "r"(b[0]), "r"(b[1]));
}
__device__ __forceinline__ void red_add_f32(float* p, float v) {
    asm volatile("red.global.add.f32 [%0], %1;" :: "l"(p), "f"(v) : "memory");
}

__device__ __forceinline__ float gelu_exact(float v) {
    return 0.5f * v * (1.0f + erff(v * 0.70710678118654752f));
}

// ---------------- 1) router (+ fused x -> fp16 conversion) ----------------
__global__ void router_kernel(const float* __restrict__ x,
                              const float* __restrict__ gw,
                              const float* __restrict__ gb,
                              float* __restrict__ probs) {
    int t = blockIdx.x * blockDim.y + threadIdx.y;
    if (t >= NTOK) return;
    int lane = threadIdx.x;
    float acc[E];
#pragma unroll
    for (int e = 0; e < E; e++) acc[e] = 0.0f;
    const float* xr = x + (size_t)t * D;
    __half* xo = g_xh + (size_t)t * D;
    for (int d = lane; d < D; d += 32) {
        float xv = xr[d];
        xo[d] = __float2half_rn(xv);             // fused conversion
        const float* g = gw + d * E;
#pragma unroll
        for (int e = 0; e < E; e++) acc[e] += xv * g[e];
    }
#pragma unroll
    for (int e = 0; e < E; e++)
#pragma unroll
        for (int off = 16; off > 0; off >>= 1)
            acc[e] += __shfl_xor_sync(0xffffffffu, acc[e], off);
    if (lane == 0) {
        float p[E]; float mx = -1e30f;
#pragma unroll
        for (int e = 0; e < E; e++) { p[e] = acc[e] + gb[e]; mx = fmaxf(mx, p[e]); }
        float s = 0.0f;
#pragma unroll
        for (int e = 0; e < E; e++) { p[e] = expf(p[e] - mx); s += p[e]; }
        float inv = 1.0f / s;
#pragma unroll
        for (int e = 0; e < E; e++) { p[e] *= inv; probs[(size_t)t * E + e] = p[e]; }
        int i0 = 0; float v0 = p[0];
#pragma unroll
        for (int e = 1; e < E; e++) if (p[e] > v0) { v0 = p[e]; i0 = e; }
        int i1 = -1; float v1 = -1.0f;
#pragma unroll
        for (int e = 0; e < E; e++) if (e != i0 && p[e] > v1) { v1 = p[e]; i1 = e; }
        float ws = 1.0f / (v0 + v1);
        g_topi[2 * t] = i0; g_topi[2 * t + 1] = i1;
        g_topw[2 * t] = v0 * ws; g_topw[2 * t + 1] = v1 * ws;
    }
}

// ---------------- 2) per-tile counts ----------------
__global__ void tilecnt_kernel() {
    __shared__ int cnt[E];
    int t = blockIdx.x * 256 + threadIdx.x;
    if (threadIdx.x < E) cnt[threadIdx.x] = 0;
    __syncthreads();
    int e0 = g_topi[2 * t], e1 = g_topi[2 * t + 1];
    int lane = threadIdx.x & 31;
#pragma unroll
    for (int e = 0; e < E; e++) {
        unsigned m = __ballot_sync(0xffffffffu, e0 == e || e1 == e);
        if (lane == 0) atomicAdd(&cnt[e], __popc(m));
    }
    __syncthreads();
    if (threadIdx.x < E) g_tilecnt[blockIdx.x][threadIdx.x] = cnt[threadIdx.x];
}

// ---------------- 3) offsets ----------------
__global__ void offsets_kernel() {
    if (threadIdx.x != 0) return;
    int tot[E];
    for (int e = 0; e < E; e++) { int s = 0; for (int b = 0; b < NTILE; b++) s += g_tilecnt[b][e]; tot[e] = s; }
    int s = 0;
    for (int e = 0; e < E; e++) { g_offs[e] = s; g_count[e] = tot[e]; s += tot[e]; }
    g_offs[E] = s;
    for (int e = 0; e < E; e++) { int r = g_offs[e]; for (int b = 0; b < NTILE; b++) { g_tileoff[b][e] = r; r += g_tilecnt[b][e]; } }
}

// ---------------- 4) deterministic scatter ----------------
__global__ void scatter_kernel() {
    __shared__ int wcnt[8][E];
    int t = blockIdx.x * 256 + threadIdx.x;
    int lane = threadIdx.x & 31, w = threadIdx.x >> 5;
    int e0 = g_topi[2 * t], e1 = g_topi[2 * t + 1];
    unsigned mask[E];
#pragma unroll
    for (int e = 0; e < E; e++) {
        mask[e] = __ballot_sync(0xffffffffu, e0 == e || e1 == e);
        if (lane == 0) wcnt[w][e] = __popc(mask[e]);
    }
    __syncthreads();
#pragma unroll
    for (int e = 0; e < E; e++) {
        if (e == e0 || e == e1) {
            int pre = 0;
            for (int ww = 0; ww < w; ww++) pre += wcnt[ww][e];
            int pos = g_tileoff[blockIdx.x][e] + pre + __popc(mask[e] & ((1u << lane) - 1));
            int which = (e == e0) ? 0 : 1;
            g_tok[pos] = t;
            g_wt[pos] = g_topw[2 * t + which];
        }
    }
}

// ---------------- 5) weight conversions (transpose + fp16) ----------------
__global__ void conv_w1_kernel(const float* __restrict__ w1) {
    __shared__ float t[32][33];
    int h0 = blockIdx.x * 32, d0 = blockIdx.y * 32, e = blockIdx.z;
#pragma unroll
    for (int i = 0; i < 4; i++) {
        int r = threadIdx.y + 8 * i;
        t[r][threadIdx.x] = w1[((size_t)e * D + d0 + r) * HH + h0 + threadIdx.x];
    }
    __syncthreads();
#pragma unroll
    for (int i = 0; i < 4; i++) {
        int r = threadIdx.y + 8 * i;
        size_t o = ((size_t)e * HH + h0 + r) * D + d0 + threadIdx.x;
        g_w1h[o] = __float2half_rn(t[threadIdx.x][r]);
    }
}
__global__ void conv_w2_kernel(const float* __restrict__ w2) {
    __shared__ float t[32][33];
    int d0 = blockIdx.x * 32, h0 = blockIdx.y * 32, e = blockIdx.z;
#pragma unroll
    for (int i = 0; i < 4; i++) {
        int r = threadIdx.y + 8 * i;
        t[r][threadIdx.x] = w2[((size_t)e * HH + h0 + r) * D + d0 + threadIdx.x];
    }
    __syncthreads();
#pragma unroll
    for (int i = 0; i < 4; i++) {
        int r = threadIdx.y + 8 * i;
        size_t o = ((size_t)e * D + d0 + r) * HH + h0 + threadIdx.x;
        g_w2h[o] = __float2half_rn(t[threadIdx.x][r]);
    }
}

// ---------------- zero-fill the combine output ----------------
__global__ void zero_out_kernel(float* __restrict__ out) {
    int i = blockIdx.x * blockDim.x + threadIdx.x;
    if (i < NTOK * (D / 4)) ((float4*)out)[i] = make_float4(0.f, 0.f, 0.f, 0.f);
}

// ---------------- 6) HMMA grouped GEMM ----------------
// CTA tile 128x128, BK=32, 4-stage cp.async pipeline, 2 CTAs/SM.
// smem per matrix: 128 rows x 40 halves (stride 80B). A|B per stage.
constexpr int MAT_B   = 128 * 80;             // 10240 B
constexpr int STAGE_B = 2 * MAT_B;            // 20480 B
constexpr int NSTAGE  = 4;
constexpr int SMEM_GEMM = 1024 + NSTAGE * STAGE_B; // 82944 B

template <int KTOT, int NFULL, bool GATHER, bool GELUQ>
__global__ __launch_bounds__(256, 2) void moe_gemm(const float* __restrict__ bias,
                                                   float* __restrict__ out) {
    constexpr int NC = KTOT / 32;
    const int e = blockIdx.z;
    const int cnt = g_count[e];
    const int m0 = blockIdx.y * 128;
    if (m0 >= cnt) return;
    const int base = g_offs[e];
    const int n0 = blockIdx.x * 128;

    extern __shared__ char smem[];
    const uint32_t sb = smem_u32(smem);
    int* s_tok = (int*)smem;               // 128 ints
    const uint32_t TILE = sb + 1024;

    const int tid = threadIdx.x;
    const int lane = tid & 31;
    const int wid = tid >> 5;
    const int wm = (wid >> 2) * 64;        // warp m offset (0,64)
    const int wn = (wid & 3) * 32;         // warp n offset (0..96)

    const __half* Ap = GATHER ? g_xh : g_hh;
    const __half* Bp = GELUQ ? g_w1h : g_w2h;

    if (tid < 128) {
        int r = base + m0 + tid; if (r > AMAX - 1) r = AMAX - 1;
        s_tok[tid] = GATHER ? g_tok[r] : r;
    }
    __syncthreads();

    // loader: 1024 16B-chunks / 256 threads = 4 per thread
    const __half* srcp[4];
    uint32_t dstoff[4];
#pragma unroll
    for (int i = 0; i < 4; i++) {
        int g = i * 256 + tid;
        int mat = g >> 9, idx = g & 511, row = idx >> 2, seg = idx & 3;
        const __half* sp;
        if (mat == 0) {
            sp = Ap + (size_t)s_tok[row] * KTOT + seg * 8;
        } else {
            sp = Bp + ((size_t)e * NFULL + n0 + row) * KTOT + seg * 8;
        }
        srcp[i] = sp;
        dstoff[i] = (uint32_t)(mat * MAT_B + row * 80 + seg * 16);
    }

    auto load_stage = [&](int c) {
        uint32_t stg = TILE + (c & 3) * STAGE_B;
        int k0 = c * 32;
#pragma unroll
        for (int i = 0; i < 4; i++) cp_async16(stg + dstoff[i], srcp[i] + k0);
    };

    float C[4][4][4];
#pragma unroll
    for (int t = 0; t < 4; t++)
#pragma unroll
        for (int n = 0; n < 4; n++)
#pragma unroll
            for (int j = 0; j < 4; j++) C[t][n][j] = 0.0f;

    load_stage(0); CP_COMMIT();
    load_stage(1); CP_COMMIT();
    load_stage(2); CP_COMMIT();

    // fragment address components
    const uint32_t a_row_off = (uint32_t)((wm + (lane & 15)) * 80 + ((lane >> 4) << 4));
    const int bq = lane >> 3, br = lane & 7;
    const uint32_t b_row_off = (uint32_t)(MAT_B + (wn + ((bq >> 1) << 3) + br) * 80 + ((bq & 1) << 4));

    for (int c = 0; c < NC; c++) {
        CP_WAIT(2);
        __syncthreads();
        if (c + 3 < NC) load_stage(c + 3);
        CP_COMMIT();

        const uint32_t stg = TILE + (c & 3) * STAGE_B;
#pragma unroll
        for (int s = 0; s < 2; s++) {           // two K=16 slices
            uint32_t af[4][4];
#pragma unroll
            for (int t = 0; t < 4; t++) {
                uint32_t ra = stg + a_row_off + t * (16 * 80) + s * 32;
                ldmatrix_x4(af[t], ra);
            }
            uint32_t bf[4][2];
#pragma unroll
            for (int nb = 0; nb < 2; nb++) {
                uint32_t rb = stg + b_row_off + nb * (16 * 80) + s * 32;
                uint32_t f[4];
                ldmatrix_x4(f, rb);
                bf[nb * 2][0] = f[0]; bf[nb * 2][1] = f[1];
                bf[nb * 2 + 1][0] = f[2]; bf[nb * 2 + 1][1] = f[3];
            }
#pragma unroll
            for (int t = 0; t < 4; t++)
#pragma unroll
                for (int n = 0; n < 4; n++)
                    mma_16816(C[t][n], af[t], bf[n]);
        }
    }

    // ---- epilogue ----
    const float* bb = bias + (size_t)e * NFULL;
#pragma unroll
    for (int t = 0; t < 4; t++) {
#pragma unroll
        for (int n = 0; n < 4; n++) {
            int row = m0 + wm + t * 16 + (lane >> 2);
            int col = n0 + wn + n * 8 + ((lane & 3) << 1);
            float b0v = bb[col], b1v = bb[col + 1];
#pragma unroll
            for (int half = 0; half < 2; half++) {
                int r = row + half * 8;
                if (r < cnt) {
                    float v0 = C[t][n][2 * half + 0] + b0v;
                    float v1 = C[t][n][2 * half + 1] + b1v;
                    if (GELUQ) {
                        size_t o = (size_t)(base + r) * NFULL + col;
                        *(__half2*)(g_hh + o) = __halves2half2(
                            __float2half_rn(gelu_exact(v0)),
                            __float2half_rn(gelu_exact(v1)));
                    } else {
                        // fused combine: exactly 2 commutative adds per output
                        // element -> bit-deterministic
                        int slot = base + r;
                        int tok = g_tok[slot];
                        float w = g_wt[slot];
                        float* op = out + (size_t)tok * NFULL + col;
                        red_add_f32(op,     w * v0);
                        red_add_f32(op + 1, w * v1);
                    }
                }
            }
        }
    }
}

// ---------------- host ----------------
extern "C" void kernel_launch(void* const* d_in, const int* in_sizes, int n_in,
                              void* d_out, int out_size) {
    const float* x      = (const float*)d_in[0];
    const float* gate_w = (const float*)d_in[1];
    const float* gate_b = (const float*)d_in[2];
    const float* w1     = (const float*)d_in[3];
    const float* b1     = (const float*)d_in[4];
    const float* w2     = (const float*)d_in[5];
    const float* b2     = (const float*)d_in[6];

    float* out   = (float*)d_out;
    float* probs = out + (size_t)NTOK * D;

    cudaFuncSetAttribute(moe_gemm<512, 1024, true, true>,
                         cudaFuncAttributeMaxDynamicSharedMemorySize, SMEM_GEMM);
    cudaFuncSetAttribute(moe_gemm<1024, 512, false, false>,
                         cudaFuncAttributeMaxDynamicSharedMemorySize, SMEM_GEMM);

    router_kernel<<<NTOK / 8, dim3(32, 8)>>>(x, gate_w, gate_b, probs);
    tilecnt_kernel<<<NTILE, 256>>>();
    offsets_kernel<<<1, 32>>>();
    scatter_kernel<<<NTILE, 256>>>();

    conv_w1_kernel<<<dim3(HH / 32, D / 32, E), dim3(32, 8)>>>(w1);
    conv_w2_kernel<<<dim3(D / 32, HH / 32, E), dim3(32, 8)>>>(w2);
    zero_out_kernel<<<(NTOK * (D / 4) + 255) / 256, 256>>>(out);

    moe_gemm<512, 1024, true, true><<<dim3(HH / 128, NTOK / 128, E), 256, SMEM_GEMM>>>(b1, out);
    moe_gemm<1024, 512, false, false><<<dim3(D / 128, NTOK / 128, E), 256, SMEM_GEMM>>>(b2, out);
}